// round 2
// baseline (speedup 1.0000x reference)
#include <cuda_runtime.h>
#include <math.h>

// Problem constants
#define B    32768
#define IN   512
#define H    512
#define KTOT 1024          // concat(x, h) reduction dim
#define NP   2048          // packed N = 4 gates * H, interleaved (j,gate)

// Packed weights: Wp[k][4*j+g]  (k<512 -> U_g[k][j], else V_g[k-512][j])
__device__ float g_Wp[(size_t)KTOT * NP];   // 8 MB scratch
__device__ float g_bp[NP];

__global__ void pack_weights(
    const float* __restrict__ Uf, const float* __restrict__ Vf, const float* __restrict__ bf,
    const float* __restrict__ Ui, const float* __restrict__ Vi, const float* __restrict__ bi,
    const float* __restrict__ Uo, const float* __restrict__ Vo, const float* __restrict__ bo,
    const float* __restrict__ Uc, const float* __restrict__ Vc, const float* __restrict__ bc)
{
    int idx = blockIdx.x * blockDim.x + threadIdx.x;
    if (idx >= KTOT * NP) return;
    int k   = idx / NP;
    int col = idx % NP;
    int j   = col >> 2;
    int g   = col & 3;     // 0=f 1=i 2=o 3=c
    const float* U = (g == 0) ? Uf : (g == 1) ? Ui : (g == 2) ? Uo : Uc;
    const float* V = (g == 0) ? Vf : (g == 1) ? Vi : (g == 2) ? Vo : Vc;
    g_Wp[idx] = (k < IN) ? U[k * H + j] : V[(k - IN) * H + j];
    if (k == 0) {
        const float* bb = (g == 0) ? bf : (g == 1) ? bi : (g == 2) ? bo : bc;
        g_bp[col] = bb[j];
    }
}

// Fused gates GEMM + LSTM epilogue.
// C[B, 2048] = concat(x,h)[B,1024] @ Wp[1024,2048], then per (b,j):
//   f,i,o = sigmoid, ch = tanh, c_new = f*c + i*ch, h_new = o*tanh(c_new)
#define BM 128
#define BN 128
#define BK 16

__global__ __launch_bounds__(256) void lstm_gates(
    const float* __restrict__ x, const float* __restrict__ h,
    const float* __restrict__ c,
    float* __restrict__ out_h, float* __restrict__ out_c)
{
    __shared__ float As[BK][BM];   // A transposed: As[k][row]
    __shared__ float Bs[BK][BN];

    const int tid = threadIdx.x;
    const int tx  = tid & 15;      // 0..15
    const int ty  = tid >> 4;      // 0..15
    const int brow = blockIdx.y * BM;
    const int bcol = blockIdx.x * BN;

    // A loader: 128 rows x 16 cols = 512 float4; 2 per thread
    const int a_row0 = tid >> 2;          // 0..63, +64
    const int a_kc   = (tid & 3) * 4;     // float4 col within BK
    // B loader: 16 rows x 128 cols = 512 float4; 2 per thread
    const int b_row0 = tid >> 5;          // 0..7, +8
    const int b_col4 = (tid & 31) * 4;

    float acc[8][8];
    #pragma unroll
    for (int i = 0; i < 8; i++)
        #pragma unroll
        for (int j = 0; j < 8; j++) acc[i][j] = 0.f;

    for (int k0 = 0; k0 < KTOT; k0 += BK) {
        // BK=16 divides 512, so the x/h split is uniform per tile
        const float* Asrc = (k0 < IN) ? (x + k0) : (h + (k0 - IN));

        #pragma unroll
        for (int i = 0; i < 2; i++) {
            int r = a_row0 + i * 64;
            float4 v = *(const float4*)(Asrc + (size_t)(brow + r) * IN + a_kc);
            As[a_kc + 0][r] = v.x;
            As[a_kc + 1][r] = v.y;
            As[a_kc + 2][r] = v.z;
            As[a_kc + 3][r] = v.w;
        }
        #pragma unroll
        for (int i = 0; i < 2; i++) {
            int r = b_row0 + i * 8;
            *(float4*)&Bs[r][b_col4] =
                *(const float4*)(g_Wp + (size_t)(k0 + r) * NP + bcol + b_col4);
        }
        __syncthreads();

        #pragma unroll
        for (int kk = 0; kk < BK; kk++) {
            float a[8], bb[8];
            #pragma unroll
            for (int i = 0; i < 4; i++) {
                a[i]      = As[kk][ty * 4 + i];
                a[i + 4]  = As[kk][64 + ty * 4 + i];
                bb[i]     = Bs[kk][tx * 4 + i];
                bb[i + 4] = Bs[kk][64 + tx * 4 + i];
            }
            #pragma unroll
            for (int i = 0; i < 8; i++)
                #pragma unroll
                for (int j = 0; j < 8; j++)
                    acc[i][j] += a[i] * bb[j];
        }
        __syncthreads();
    }

    // Epilogue: each thread owns 8 rows x 2 j-groups (each group = 4 gates)
    #pragma unroll
    for (int rm = 0; rm < 8; rm++) {
        int row = brow + ((rm < 4) ? (ty * 4 + rm) : (64 + ty * 4 + rm - 4));
        #pragma unroll
        for (int q = 0; q < 2; q++) {
            int cb = bcol + (q ? 64 : 0) + tx * 4;   // packed col of gate f
            int j  = cb >> 2;
            float pf = acc[rm][q * 4 + 0] + g_bp[cb + 0];
            float pi = acc[rm][q * 4 + 1] + g_bp[cb + 1];
            float po = acc[rm][q * 4 + 2] + g_bp[cb + 2];
            float pc = acc[rm][q * 4 + 3] + g_bp[cb + 3];
            float f_ = 1.f / (1.f + expf(-pf));
            float i_ = 1.f / (1.f + expf(-pi));
            float o_ = 1.f / (1.f + expf(-po));
            float ch = tanhf(pc);
            float c_old = c[(size_t)row * H + j];
            float cn = f_ * c_old + i_ * ch;
            float hn = o_ * tanhf(cn);
            out_h[(size_t)row * H + j] = hn;
            out_c[(size_t)row * H + j] = cn;
        }
    }
}

// logits = h_new @ W_out[512,2] + b_out; softmax over 2 classes. One warp/row.
__global__ void head_kernel(const float* __restrict__ hbuf,
                            const float* __restrict__ Wout,
                            const float* __restrict__ bout,
                            float* __restrict__ pre_label)
{
    int warp = (blockIdx.x * blockDim.x + threadIdx.x) >> 5;
    int lane = threadIdx.x & 31;
    if (warp >= B) return;
    const float* row = hbuf + (size_t)warp * H;
    float s0 = 0.f, s1 = 0.f;
    #pragma unroll 4
    for (int j = lane; j < H; j += 32) {
        float v = row[j];
        s0 += v * Wout[j * 2 + 0];
        s1 += v * Wout[j * 2 + 1];
    }
    #pragma unroll
    for (int off = 16; off; off >>= 1) {
        s0 += __shfl_xor_sync(0xffffffffu, s0, off);
        s1 += __shfl_xor_sync(0xffffffffu, s1, off);
    }
    if (lane == 0) {
        s0 += bout[0];
        s1 += bout[1];
        float m  = fmaxf(s0, s1);
        float e0 = expf(s0 - m), e1 = expf(s1 - m);
        float inv = 1.f / (e0 + e1);
        pre_label[warp * 2 + 0] = e0 * inv;
        pre_label[warp * 2 + 1] = e1 * inv;
    }
}

extern "C" void kernel_launch(void* const* d_in, const int* in_sizes, int n_in,
                              void* d_out, int out_size)
{
    const float* x    = (const float*)d_in[0];
    const float* h    = (const float*)d_in[1];
    const float* c    = (const float*)d_in[2];
    const float* Uf   = (const float*)d_in[3];
    const float* Vf   = (const float*)d_in[4];
    const float* bf   = (const float*)d_in[5];
    const float* Ui   = (const float*)d_in[6];
    const float* Vi   = (const float*)d_in[7];
    const float* bi   = (const float*)d_in[8];
    const float* Uo   = (const float*)d_in[9];
    const float* Vo   = (const float*)d_in[10];
    const float* bo   = (const float*)d_in[11];
    const float* Uc   = (const float*)d_in[12];
    const float* Vc   = (const float*)d_in[13];
    const float* bc   = (const float*)d_in[14];
    const float* Wout = (const float*)d_in[15];
    const float* bout = (const float*)d_in[16];

    float* out       = (float*)d_out;
    float* pre_label = out;                          // [B,2]
    float* out_h     = out + (size_t)B * 2;          // [B,512]
    float* out_c     = out_h + (size_t)B * H;        // [B,512]

    pack_weights<<<(KTOT * NP + 255) / 256, 256>>>(Uf, Vf, bf, Ui, Vi, bi,
                                                   Uo, Vo, bo, Uc, Vc, bc);
    lstm_gates<<<dim3(NP / BN, B / BM), 256>>>(x, h, c, out_h, out_c);
    head_kernel<<<(B * 32 + 255) / 256, 256>>>(out_h, Wout, bout, pre_label);
}

// round 10
// speedup vs baseline: 1.8224x; 1.8224x over previous
#include <cuda_runtime.h>
#include <cuda_bf16.h>
#include <cstdint>
#include <math.h>

// Problem constants
#define BSZ   32768
#define HDIM  512
#define KTOT  1024          // concat(x,h)
#define NPK   2048          // 4 gates * 512, interleaved (j,gate): col = 4*j+g

// GEMM tiling (warp-level mma.sync path; base-PTX features only)
#define BM    128           // rows per CTA
#define BN    128           // packed cols per CTA (= 32 j's)
#define BK    32            // K per chunk (per term)
#define NCH   (KTOT / BK)   // 32 chunks
#define NST   3             // cp.async pipeline stages

// Packed operands: per row, K chunked: [chunk][hi x32 | lo x32] bf16 = 128B/chunk
#define KPACK (NCH * 64)    // 2048 bf16 per row

__device__ __nv_bfloat16 g_Apk[(size_t)BSZ * KPACK];   // 128 MB
__device__ __nv_bfloat16 g_Bpk[(size_t)NPK * KPACK];   // 8 MB
__device__ float         g_bp[NPK];

// ---------------------------------------------------------------- helpers
__device__ __forceinline__ uint32_t smem_u32(const void* p) {
    uint32_t a;
    asm("{ .reg .u64 t; cvta.to.shared.u64 t, %1; cvt.u32.u64 %0, t; }" : "=r"(a) : "l"(p));
    return a;
}
__device__ __forceinline__ uint32_t swz(uint32_t off) {   // SW128-style xor swizzle
    return off ^ ((off >> 3) & 0x70);
}
__device__ __forceinline__ void cpa16(uint32_t dst, const void* src) {
    asm volatile("cp.async.cg.shared.global [%0], [%1], 16;" :: "r"(dst), "l"(src) : "memory");
}
__device__ __forceinline__ void cpa_commit() { asm volatile("cp.async.commit_group;" ::: "memory"); }
__device__ __forceinline__ void cpa_wait2()  { asm volatile("cp.async.wait_group 2;" ::: "memory"); }
__device__ __forceinline__ void cpa_wait1()  { asm volatile("cp.async.wait_group 1;" ::: "memory"); }
__device__ __forceinline__ void cpa_wait0()  { asm volatile("cp.async.wait_group 0;" ::: "memory"); }

__device__ __forceinline__ void ldsm4(uint32_t* r, uint32_t addr) {
    asm volatile("ldmatrix.sync.aligned.m8n8.x4.shared.b16 {%0,%1,%2,%3}, [%4];"
        : "=r"(r[0]), "=r"(r[1]), "=r"(r[2]), "=r"(r[3]) : "r"(addr));
}
__device__ __forceinline__ void ldsm2(uint32_t* r, uint32_t addr) {
    asm volatile("ldmatrix.sync.aligned.m8n8.x2.shared.b16 {%0,%1}, [%2];"
        : "=r"(r[0]), "=r"(r[1]) : "r"(addr));
}
__device__ __forceinline__ void mma16816(float* d, const uint32_t* a, const uint32_t* b) {
    asm volatile(
        "mma.sync.aligned.m16n8k16.row.col.f32.bf16.bf16.f32 "
        "{%0,%1,%2,%3}, {%4,%5,%6,%7}, {%8,%9}, {%0,%1,%2,%3};"
        : "+f"(d[0]), "+f"(d[1]), "+f"(d[2]), "+f"(d[3])
        : "r"(a[0]), "r"(a[1]), "r"(a[2]), "r"(a[3]), "r"(b[0]), "r"(b[1]));
}

// ---------------------------------------------------------------- pre-passes
__global__ void conv_A(const float* __restrict__ x, const float* __restrict__ h) {
    size_t idx = (size_t)blockIdx.x * blockDim.x + threadIdx.x;
    if (idx >= (size_t)BSZ * KTOT) return;
    int k   = (int)(idx & (KTOT - 1));
    int row = (int)(idx >> 10);
    float v = (k < HDIM) ? x[(size_t)row * HDIM + k] : h[(size_t)row * HDIM + (k - HDIM)];
    __nv_bfloat16 hi = __float2bfloat16(v);
    __nv_bfloat16 lo = __float2bfloat16(v - __bfloat162float(hi));
    size_t base = (size_t)row * KPACK + (size_t)(k >> 5) * 64 + (k & 31);
    g_Apk[base] = hi;
    g_Apk[base + 32] = lo;
}

__global__ void pack_W(
    const float* __restrict__ Uf, const float* __restrict__ Vf, const float* __restrict__ bf,
    const float* __restrict__ Ui, const float* __restrict__ Vi, const float* __restrict__ bi,
    const float* __restrict__ Uo, const float* __restrict__ Vo, const float* __restrict__ bo,
    const float* __restrict__ Uc, const float* __restrict__ Vc, const float* __restrict__ bc)
{
    int idx = blockIdx.x * blockDim.x + threadIdx.x;   // over KTOT*HDIM
    if (idx >= KTOT * HDIM) return;
    int j = idx & (HDIM - 1);
    int k = idx >> 9;
    const float* Us[4] = {Uf, Ui, Uo, Uc};
    const float* Vs[4] = {Vf, Vi, Vo, Vc};
    const float* bs[4] = {bf, bi, bo, bc};
    #pragma unroll
    for (int g = 0; g < 4; g++) {
        float v = (k < HDIM) ? Us[g][(size_t)k * HDIM + j]
                             : Vs[g][(size_t)(k - HDIM) * HDIM + j];
        __nv_bfloat16 hi = __float2bfloat16(v);
        __nv_bfloat16 lo = __float2bfloat16(v - __bfloat162float(hi));
        size_t n = (size_t)(4 * j + g);
        size_t base = n * KPACK + (size_t)(k >> 5) * 64 + (k & 31);
        g_Bpk[base] = hi;
        g_Bpk[base + 32] = lo;
        if (k == 0) g_bp[4 * j + g] = bs[g][j];
    }
}

// ---------------------------------------------------------------- main GEMM
// SMEM stage (32KB): A tile 128 rows x 128B (hi|lo), then B tile 128 rows x 128B.
#define STAGE_BYTES 32768
#define SMEM_TOTAL  (NST * STAGE_BYTES)

__device__ __forceinline__ void load_chunk(uint32_t ab,
                                           const __nv_bfloat16* Asrc,
                                           const __nv_bfloat16* Bsrc,
                                           int c, int tid)
{
    const char* ap = (const char*)Asrc;
    const char* bp = (const char*)Bsrc;
    #pragma unroll
    for (int kq = 0; kq < 4; kq++) {
        int q = tid + 256 * kq;        // 0..1023 : 128 rows x 8 16B-units
        int r = q >> 3, u = q & 7;
        uint32_t off = (uint32_t)(r << 7) + (uint32_t)(u << 4);
        uint32_t sw = swz(off);
        size_t go = ((size_t)r << 12) + ((size_t)c << 7) + ((size_t)u << 4);
        cpa16(ab + sw, ap + go);
        cpa16(ab + 16384 + sw, bp + go);
    }
}

__global__ void __launch_bounds__(256, 1) lstm_gemm(
    const float* __restrict__ c_in,
    float* __restrict__ out_h, float* __restrict__ out_c)
{
    extern __shared__ char smem[];
    uint32_t sb = smem_u32(smem);
    const int tid  = threadIdx.x;
    const int lane = tid & 31;
    const int wid  = tid >> 5;
    const int wm   = wid & 1;      // 2 warp-rows of 64
    const int wn   = wid >> 1;     // 4 warp-cols of 32
    const int brow = blockIdx.y * BM;
    const int bcol = blockIdx.x * BN;

    const __nv_bfloat16* Asrc = g_Apk + (size_t)brow * KPACK;
    const __nv_bfloat16* Bsrc = g_Bpk + (size_t)bcol * KPACK;

    float acc[4][4][4];
    #pragma unroll
    for (int mt = 0; mt < 4; mt++)
        #pragma unroll
        for (int nt = 0; nt < 4; nt++)
            #pragma unroll
            for (int e = 0; e < 4; e++) acc[mt][nt][e] = 0.f;

    // prologue: fill 3 stages
    load_chunk(sb + 0 * STAGE_BYTES, Asrc, Bsrc, 0, tid); cpa_commit();
    load_chunk(sb + 1 * STAGE_BYTES, Asrc, Bsrc, 1, tid); cpa_commit();
    load_chunk(sb + 2 * STAGE_BYTES, Asrc, Bsrc, 2, tid); cpa_commit();

    // ldmatrix address components (constant across chunks)
    const int a_row = wm * 64 + (lane & 15);          // + mt*16
    const int a_cb  = (lane >> 4) * 16;               // + ks*32 (+64 for lo)
    const int b_row = wn * 32 + (lane & 7);           // + nt*8
    const int b_cb  = ((lane >> 3) & 1) * 16;         // + ks*32 (+64 for lo)

    for (int i = 0; i < NCH; i++) {
        int s = i % 3;
        if (i < NCH - 2)       cpa_wait2();
        else if (i == NCH - 2) cpa_wait1();
        else                   cpa_wait0();
        __syncthreads();

        uint32_t abase = sb + s * STAGE_BYTES;
        uint32_t bbase = abase + 16384;

        #pragma unroll
        for (int ks = 0; ks < 2; ks++) {
            uint32_t ah[4][4], al[4][4], bh[4][2], bl[4][2];
            #pragma unroll
            for (int mt = 0; mt < 4; mt++) {
                uint32_t roff = (uint32_t)((a_row + mt * 16) << 7);
                ldsm4(ah[mt], abase + swz(roff + (uint32_t)(a_cb + ks * 32)));
                ldsm4(al[mt], abase + swz(roff + (uint32_t)(a_cb + ks * 32 + 64)));
            }
            #pragma unroll
            for (int nt = 0; nt < 4; nt++) {
                uint32_t roff = (uint32_t)((b_row + nt * 8) << 7);
                ldsm2(bh[nt], bbase + swz(roff + (uint32_t)(b_cb + ks * 32)));
                ldsm2(bl[nt], bbase + swz(roff + (uint32_t)(b_cb + ks * 32 + 64)));
            }
            #pragma unroll
            for (int mt = 0; mt < 4; mt++)
                #pragma unroll
                for (int nt = 0; nt < 4; nt++) {
                    mma16816(acc[mt][nt], ah[mt], bh[nt]);   // hi*hi
                    mma16816(acc[mt][nt], ah[mt], bl[nt]);   // hi*lo
                    mma16816(acc[mt][nt], al[mt], bh[nt]);   // lo*hi
                }
        }
        __syncthreads();

        if (i + 3 < NCH) {
            load_chunk(sb + s * STAGE_BYTES, Asrc, Bsrc, i + 3, tid);
            cpa_commit();
        }
    }

    // -------- epilogue: gates in registers, h/c staged via SMEM (coalesced)
    __syncthreads();
    float* shC = (float*)smem;            // [128][33]
    float* shH = shC + 128 * 33;          // [128][33]
    const int j0 = bcol >> 2;             // 32 j's per CTA

    for (int idx = tid; idx < 128 * 32; idx += 256) {
        int r = idx >> 5, j = idx & 31;
        shC[r * 33 + j] = c_in[(size_t)(brow + r) * HDIM + j0 + j];
    }
    __syncthreads();

    #pragma unroll
    for (int mt = 0; mt < 4; mt++) {
        #pragma unroll
        for (int nt = 0; nt < 4; nt++) {
            int nb = wn * 32 + nt * 8 + 2 * (lane & 3);   // local packed col (pair base)
            float bA = __ldg(&g_bp[bcol + nb]);
            float bB = __ldg(&g_bp[bcol + nb + 1]);
            #pragma unroll
            for (int hf = 0; hf < 2; hf++) {
                int row = wm * 64 + mt * 16 + (lane >> 2) + hf * 8;
                float p0 = acc[mt][nt][2 * hf + 0] + bA;
                float p1 = acc[mt][nt][2 * hf + 1] + bB;
                float q0 = __shfl_xor_sync(0xffffffffu, p0, 1);
                float q1 = __shfl_xor_sync(0xffffffffu, p1, 1);
                if ((lane & 1) == 0) {
                    // even lane holds (f,i); partner lane holds (o,c)
                    float fg = 1.f / (1.f + __expf(-p0));
                    float ig = 1.f / (1.f + __expf(-p1));
                    float og = 1.f / (1.f + __expf(-q0));
                    float ch = tanhf(q1);
                    int jl = nb >> 2;
                    float co = shC[row * 33 + jl];
                    float cn = fg * co + ig * ch;
                    float hn = og * tanhf(cn);
                    shC[row * 33 + jl] = cn;
                    shH[row * 33 + jl] = hn;
                }
            }
        }
    }
    __syncthreads();

    for (int idx = tid; idx < 128 * 32; idx += 256) {
        int r = idx >> 5, j = idx & 31;
        size_t go = (size_t)(brow + r) * HDIM + j0 + j;
        out_h[go] = shH[r * 33 + j];
        out_c[go] = shC[r * 33 + j];
    }
}

// ---------------------------------------------------------------- head
__global__ void head_kernel(const float* __restrict__ hbuf,
                            const float* __restrict__ Wout,
                            const float* __restrict__ bout,
                            float* __restrict__ pre_label)
{
    int warp = (blockIdx.x * blockDim.x + threadIdx.x) >> 5;
    int lane = threadIdx.x & 31;
    if (warp >= BSZ) return;
    const float* row = hbuf + (size_t)warp * HDIM;
    float s0 = 0.f, s1 = 0.f;
    #pragma unroll 4
    for (int j = lane; j < HDIM; j += 32) {
        float v = row[j];
        s0 += v * Wout[j * 2 + 0];
        s1 += v * Wout[j * 2 + 1];
    }
    #pragma unroll
    for (int off = 16; off; off >>= 1) {
        s0 += __shfl_xor_sync(0xffffffffu, s0, off);
        s1 += __shfl_xor_sync(0xffffffffu, s1, off);
    }
    if (lane == 0) {
        s0 += bout[0];
        s1 += bout[1];
        float mx = fmaxf(s0, s1);
        float e0 = __expf(s0 - mx), e1 = __expf(s1 - mx);
        float inv = 1.f / (e0 + e1);
        pre_label[warp * 2 + 0] = e0 * inv;
        pre_label[warp * 2 + 1] = e1 * inv;
    }
}

// ---------------------------------------------------------------- launch
extern "C" void kernel_launch(void* const* d_in, const int* in_sizes, int n_in,
                              void* d_out, int out_size)
{
    const float* x    = (const float*)d_in[0];
    const float* h    = (const float*)d_in[1];
    const float* c    = (const float*)d_in[2];
    const float* Uf   = (const float*)d_in[3];
    const float* Vf   = (const float*)d_in[4];
    const float* bf   = (const float*)d_in[5];
    const float* Ui   = (const float*)d_in[6];
    const float* Vi   = (const float*)d_in[7];
    const float* bi   = (const float*)d_in[8];
    const float* Uo   = (const float*)d_in[9];
    const float* Vo   = (const float*)d_in[10];
    const float* bo   = (const float*)d_in[11];
    const float* Uc   = (const float*)d_in[12];
    const float* Vc   = (const float*)d_in[13];
    const float* bc   = (const float*)d_in[14];
    const float* Wout = (const float*)d_in[15];
    const float* bout = (const float*)d_in[16];

    float* out       = (float*)d_out;
    float* pre_label = out;                       // [B,2]
    float* out_h     = out + (size_t)BSZ * 2;     // [B,512]
    float* out_c     = out_h + (size_t)BSZ * HDIM;

    cudaFuncSetAttribute(lstm_gemm, cudaFuncAttributeMaxDynamicSharedMemorySize, SMEM_TOTAL);

    pack_W<<<(KTOT * HDIM + 255) / 256, 256>>>(Uf, Vf, bf, Ui, Vi, bi,
                                               Uo, Vo, bo, Uc, Vc, bc);
    conv_A<<<(int)(((size_t)BSZ * KTOT + 255) / 256), 256>>>(x, h);
    lstm_gemm<<<dim3(NPK / BN, BSZ / BM), 256, SMEM_TOTAL>>>(c, out_h, out_c);
    head_kernel<<<(BSZ * 32 + 255) / 256, 256>>>(out_h, Wout, bout, pre_label);
}

// round 11
// speedup vs baseline: 1.9455x; 1.0675x over previous
#include <cuda_runtime.h>
#include <cuda_bf16.h>
#include <cstdint>
#include <math.h>

// Problem constants
#define BSZ   32768
#define HDIM  512
#define KTOT  1024          // concat(x,h)
#define NPK   2048          // 4 gates * 512, interleaved (j,gate): col = 4*j+g

// GEMM tiling (warp-level mma.sync path; base-PTX features only)
#define BM    128           // rows per CTA
#define BN    128           // packed cols per CTA (= 32 j's)
#define BK    64            // K per iteration (two 32-K packed chunks)
#define NCH   (KTOT / BK)   // 16 iterations
#define NST   3             // cp.async pipeline stages

// Packed operands: per row, K chunked: [chunk32][hi x32 | lo x32] bf16 = 128B/chunk
#define KPACK (32 * 64)     // 2048 bf16 per row (32 packed chunks)

__device__ __nv_bfloat16 g_Apk[(size_t)BSZ * KPACK];   // 128 MB
__device__ __nv_bfloat16 g_Bpk[(size_t)NPK * KPACK];   // 8 MB
__device__ float         g_bp[NPK];

// ---------------------------------------------------------------- helpers
__device__ __forceinline__ uint32_t smem_u32(const void* p) {
    uint32_t a;
    asm("{ .reg .u64 t; cvta.to.shared.u64 t, %1; cvt.u32.u64 %0, t; }" : "=r"(a) : "l"(p));
    return a;
}
__device__ __forceinline__ uint32_t swz(uint32_t off) {   // SW128-style xor swizzle
    return off ^ ((off >> 3) & 0x70);
}
__device__ __forceinline__ void cpa16(uint32_t dst, const void* src) {
    asm volatile("cp.async.cg.shared.global [%0], [%1], 16;" :: "r"(dst), "l"(src) : "memory");
}
__device__ __forceinline__ void cpa_commit() { asm volatile("cp.async.commit_group;" ::: "memory"); }
__device__ __forceinline__ void cpa_wait1()  { asm volatile("cp.async.wait_group 1;" ::: "memory"); }
__device__ __forceinline__ void cpa_wait0()  { asm volatile("cp.async.wait_group 0;" ::: "memory"); }

__device__ __forceinline__ void ldsm4(uint32_t* r, uint32_t addr) {
    asm volatile("ldmatrix.sync.aligned.m8n8.x4.shared.b16 {%0,%1,%2,%3}, [%4];"
        : "=r"(r[0]), "=r"(r[1]), "=r"(r[2]), "=r"(r[3]) : "r"(addr));
}
__device__ __forceinline__ void mma16816(float* d, const uint32_t* a, const uint32_t* b) {
    asm volatile(
        "mma.sync.aligned.m16n8k16.row.col.f32.bf16.bf16.f32 "
        "{%0,%1,%2,%3}, {%4,%5,%6,%7}, {%8,%9}, {%0,%1,%2,%3};"
        : "+f"(d[0]), "+f"(d[1]), "+f"(d[2]), "+f"(d[3])
        : "r"(a[0]), "r"(a[1]), "r"(a[2]), "r"(a[3]), "r"(b[0]), "r"(b[1]));
}

// ---------------------------------------------------------------- pre-passes
// Vectorized: each thread converts 8 consecutive k's (16B hi write + 16B lo write).
__global__ void conv_A(const float* __restrict__ x, const float* __restrict__ h) {
    size_t t = (size_t)blockIdx.x * blockDim.x + threadIdx.x;
    if (t >= (size_t)BSZ * (KTOT / 8)) return;
    int row = (int)(t >> 7);            // KTOT/8 = 128 groups per row
    int kg  = ((int)t & 127) * 8;
    const float* src = (kg < HDIM) ? (x + (size_t)row * HDIM + kg)
                                   : (h + (size_t)row * HDIM + (kg - HDIM));
    float4 v0 = *(const float4*)(src);
    float4 v1 = *(const float4*)(src + 4);
    float v[8] = {v0.x, v0.y, v0.z, v0.w, v1.x, v1.y, v1.z, v1.w};
    __nv_bfloat16 hi[8], lo[8];
    #pragma unroll
    for (int e = 0; e < 8; e++) {
        hi[e] = __float2bfloat16(v[e]);
        lo[e] = __float2bfloat16(v[e] - __bfloat162float(hi[e]));
    }
    size_t base = (size_t)row * KPACK + (size_t)(kg >> 5) * 64 + (kg & 31);
    *(uint4*)&g_Apk[base]      = *(uint4*)hi;
    *(uint4*)&g_Apk[base + 32] = *(uint4*)lo;
}

__global__ void pack_W(
    const float* __restrict__ Uf, const float* __restrict__ Vf, const float* __restrict__ bf,
    const float* __restrict__ Ui, const float* __restrict__ Vi, const float* __restrict__ bi,
    const float* __restrict__ Uo, const float* __restrict__ Vo, const float* __restrict__ bo,
    const float* __restrict__ Uc, const float* __restrict__ Vc, const float* __restrict__ bc)
{
    int idx = blockIdx.x * blockDim.x + threadIdx.x;   // over KTOT*HDIM
    if (idx >= KTOT * HDIM) return;
    int j = idx & (HDIM - 1);
    int k = idx >> 9;
    const float* Us[4] = {Uf, Ui, Uo, Uc};
    const float* Vs[4] = {Vf, Vi, Vo, Vc};
    const float* bs[4] = {bf, bi, bo, bc};
    #pragma unroll
    for (int g = 0; g < 4; g++) {
        float v = (k < HDIM) ? Us[g][(size_t)k * HDIM + j]
                             : Vs[g][(size_t)(k - HDIM) * HDIM + j];
        __nv_bfloat16 hi = __float2bfloat16(v);
        __nv_bfloat16 lo = __float2bfloat16(v - __bfloat162float(hi));
        size_t n = (size_t)(4 * j + g);
        size_t base = n * KPACK + (size_t)(k >> 5) * 64 + (k & 31);
        g_Bpk[base] = hi;
        g_Bpk[base + 32] = lo;
        if (k == 0) g_bp[4 * j + g] = bs[g][j];
    }
}

// ---------------------------------------------------------------- main GEMM
// Stage (64KB): A sub0 16KB | A sub1 16KB | B sub0 16KB | B sub1 16KB
// Each sub-tile: 128 rows x 128B (hi32|lo32 bf16), xor-swizzled per row.
#define STAGE_BYTES 65536
#define SMEM_TOTAL  (NST * STAGE_BYTES)

__device__ __forceinline__ void load_chunk(uint32_t st,
                                           const __nv_bfloat16* Asrc,
                                           const __nv_bfloat16* Bsrc,
                                           int c, int tid)
{
    // Per iteration: A 32KB + B 32KB. 256 threads x 16 cpa16.
    const char* ap = (const char*)Asrc;
    const char* bp = (const char*)Bsrc;
    #pragma unroll
    for (int kq = 0; kq < 8; kq++) {
        int q   = tid + 256 * kq;              // 0..2047 over A's 16B units
        int sub = q >> 10;                     // which 128B sub-chunk
        int r   = (q >> 3) & 127;
        int u   = q & 7;
        uint32_t soff = (uint32_t)(sub << 14) + swz((uint32_t)(r << 7) + (uint32_t)(u << 4));
        size_t go = ((size_t)r << 12) + ((size_t)c << 8) + ((size_t)sub << 7) + ((size_t)u << 4);
        cpa16(st + soff, ap + go);
        cpa16(st + 32768 + soff, bp + go);
    }
}

__global__ void __launch_bounds__(256, 1) lstm_gemm(
    const float* __restrict__ c_in,
    float* __restrict__ out_h, float* __restrict__ out_c)
{
    extern __shared__ char smem[];
    uint32_t sb = smem_u32(smem);
    const int tid  = threadIdx.x;
    const int lane = tid & 31;
    const int wid  = tid >> 5;
    const int wm   = wid & 1;      // 2 warp-rows of 64
    const int wn   = wid >> 1;     // 4 warp-cols of 32
    const int brow = blockIdx.y * BM;
    const int bcol = blockIdx.x * BN;

    const __nv_bfloat16* Asrc = g_Apk + (size_t)brow * KPACK;
    const __nv_bfloat16* Bsrc = g_Bpk + (size_t)bcol * KPACK;

    float acc[4][4][4];
    #pragma unroll
    for (int mt = 0; mt < 4; mt++)
        #pragma unroll
        for (int nt = 0; nt < 4; nt++)
            #pragma unroll
            for (int e = 0; e < 4; e++) acc[mt][nt][e] = 0.f;

    // prologue: fill NST-1 = 2 stages
    load_chunk(sb + 0 * STAGE_BYTES, Asrc, Bsrc, 0, tid); cpa_commit();
    load_chunk(sb + 1 * STAGE_BYTES, Asrc, Bsrc, 1, tid); cpa_commit();

    // ldmatrix address components
    const int a_row = wm * 64 + (lane & 15);                              // + mt*16
    const int a_kb  = (lane >> 4) * 16;                                   // k-half select (bytes)
    const int b_row = (lane & 7) + ((lane >> 4) & 1) * 8;                 // + wn*32 + ntp*16
    const int b_kb  = ((lane >> 3) & 1) * 16;                             // k-half select (bytes)

    for (int i = 0; i < NCH; i++) {
        if (i == NCH - 1) cpa_wait0(); else cpa_wait1();
        __syncthreads();

        if (i + 2 < NCH) {
            load_chunk(sb + ((i + 2) % 3) * STAGE_BYTES, Asrc, Bsrc, i + 2, tid);
            cpa_commit();
        }

        uint32_t st = sb + (i % 3) * STAGE_BYTES;

        #pragma unroll
        for (int ks = 0; ks < 4; ks++) {
            uint32_t asub = st + (uint32_t)((ks >> 1) << 14);
            uint32_t bsub = st + 32768 + (uint32_t)((ks >> 1) << 14);
            uint32_t kk   = (uint32_t)((ks & 1) * 32);                    // bytes within hi region

            uint32_t ah[4][4], al[4][4], bh[4][2], bl[4][2];
            #pragma unroll
            for (int mt = 0; mt < 4; mt++) {
                uint32_t roff = (uint32_t)((a_row + mt * 16) << 7);
                ldsm4(ah[mt], asub + swz(roff + (uint32_t)a_kb + kk));
                ldsm4(al[mt], asub + swz(roff + (uint32_t)a_kb + kk + 64));
            }
            #pragma unroll
            for (int ntp = 0; ntp < 2; ntp++) {
                uint32_t roff = (uint32_t)((wn * 32 + ntp * 16 + b_row) << 7);
                uint32_t t4[4];
                ldsm4(t4, bsub + swz(roff + (uint32_t)b_kb + kk));
                bh[2 * ntp][0] = t4[0]; bh[2 * ntp][1] = t4[1];
                bh[2 * ntp + 1][0] = t4[2]; bh[2 * ntp + 1][1] = t4[3];
                ldsm4(t4, bsub + swz(roff + (uint32_t)b_kb + kk + 64));
                bl[2 * ntp][0] = t4[0]; bl[2 * ntp][1] = t4[1];
                bl[2 * ntp + 1][0] = t4[2]; bl[2 * ntp + 1][1] = t4[3];
            }
            #pragma unroll
            for (int mt = 0; mt < 4; mt++)
                #pragma unroll
                for (int nt = 0; nt < 4; nt++) {
                    mma16816(acc[mt][nt], ah[mt], bh[nt]);   // hi*hi
                    mma16816(acc[mt][nt], ah[mt], bl[nt]);   // hi*lo
                    mma16816(acc[mt][nt], al[mt], bh[nt]);   // lo*hi
                }
        }
    }

    // -------- epilogue: gates in registers, h/c staged via SMEM (coalesced)
    __syncthreads();
    float* shC = (float*)smem;            // [128][33]
    float* shH = shC + 128 * 33;          // [128][33]
    const int j0 = bcol >> 2;             // 32 j's per CTA

    for (int idx = tid; idx < 128 * 32; idx += 256) {
        int r = idx >> 5, j = idx & 31;
        shC[r * 33 + j] = c_in[(size_t)(brow + r) * HDIM + j0 + j];
    }
    __syncthreads();

    #pragma unroll
    for (int mt = 0; mt < 4; mt++) {
        #pragma unroll
        for (int nt = 0; nt < 4; nt++) {
            int nb = wn * 32 + nt * 8 + 2 * (lane & 3);   // local packed col (pair base)
            float bA = __ldg(&g_bp[bcol + nb]);
            float bB = __ldg(&g_bp[bcol + nb + 1]);
            #pragma unroll
            for (int hf = 0; hf < 2; hf++) {
                int row = wm * 64 + mt * 16 + (lane >> 2) + hf * 8;
                float p0 = acc[mt][nt][2 * hf + 0] + bA;
                float p1 = acc[mt][nt][2 * hf + 1] + bB;
                float q0 = __shfl_xor_sync(0xffffffffu, p0, 1);
                float q1 = __shfl_xor_sync(0xffffffffu, p1, 1);
                if ((lane & 1) == 0) {
                    // even lane holds (f,i); partner lane holds (o,c)
                    float fg = 1.f / (1.f + __expf(-p0));
                    float ig = 1.f / (1.f + __expf(-p1));
                    float og = 1.f / (1.f + __expf(-q0));
                    float ch = tanhf(q1);
                    int jl = nb >> 2;
                    float co = shC[row * 33 + jl];
                    float cn = fg * co + ig * ch;
                    float hn = og * tanhf(cn);
                    shC[row * 33 + jl] = cn;
                    shH[row * 33 + jl] = hn;
                }
            }
        }
    }
    __syncthreads();

    for (int idx = tid; idx < 128 * 32; idx += 256) {
        int r = idx >> 5, j = idx & 31;
        size_t go = (size_t)(brow + r) * HDIM + j0 + j;
        out_h[go] = shH[r * 33 + j];
        out_c[go] = shC[r * 33 + j];
    }
}

// ---------------------------------------------------------------- head
__global__ void head_kernel(const float* __restrict__ hbuf,
                            const float* __restrict__ Wout,
                            const float* __restrict__ bout,
                            float* __restrict__ pre_label)
{
    int warp = (blockIdx.x * blockDim.x + threadIdx.x) >> 5;
    int lane = threadIdx.x & 31;
    if (warp >= BSZ) return;
    const float* row = hbuf + (size_t)warp * HDIM;
    float s0 = 0.f, s1 = 0.f;
    #pragma unroll 4
    for (int j = lane; j < HDIM; j += 32) {
        float v = row[j];
        s0 += v * Wout[j * 2 + 0];
        s1 += v * Wout[j * 2 + 1];
    }
    #pragma unroll
    for (int off = 16; off; off >>= 1) {
        s0 += __shfl_xor_sync(0xffffffffu, s0, off);
        s1 += __shfl_xor_sync(0xffffffffu, s1, off);
    }
    if (lane == 0) {
        s0 += bout[0];
        s1 += bout[1];
        float mx = fmaxf(s0, s1);
        float e0 = __expf(s0 - mx), e1 = __expf(s1 - mx);
        float inv = 1.f / (e0 + e1);
        pre_label[warp * 2 + 0] = e0 * inv;
        pre_label[warp * 2 + 1] = e1 * inv;
    }
}

// ---------------------------------------------------------------- launch
extern "C" void kernel_launch(void* const* d_in, const int* in_sizes, int n_in,
                              void* d_out, int out_size)
{
    const float* x    = (const float*)d_in[0];
    const float* h    = (const float*)d_in[1];
    const float* c    = (const float*)d_in[2];
    const float* Uf   = (const float*)d_in[3];
    const float* Vf   = (const float*)d_in[4];
    const float* bf   = (const float*)d_in[5];
    const float* Ui   = (const float*)d_in[6];
    const float* Vi   = (const float*)d_in[7];
    const float* bi   = (const float*)d_in[8];
    const float* Uo   = (const float*)d_in[9];
    const float* Vo   = (const float*)d_in[10];
    const float* bo   = (const float*)d_in[11];
    const float* Uc   = (const float*)d_in[12];
    const float* Vc   = (const float*)d_in[13];
    const float* bc   = (const float*)d_in[14];
    const float* Wout = (const float*)d_in[15];
    const float* bout = (const float*)d_in[16];

    float* out       = (float*)d_out;
    float* pre_label = out;                       // [B,2]
    float* out_h     = out + (size_t)BSZ * 2;     // [B,512]
    float* out_c     = out_h + (size_t)BSZ * HDIM;

    cudaFuncSetAttribute(lstm_gemm, cudaFuncAttributeMaxDynamicSharedMemorySize, SMEM_TOTAL);

    pack_W<<<(KTOT * HDIM + 255) / 256, 256>>>(Uf, Vf, bf, Ui, Vi, bi,
                                               Uo, Vo, bo, Uc, Vc, bc);
    conv_A<<<(int)(((size_t)BSZ * (KTOT / 8) + 255) / 256), 256>>>(x, h);
    lstm_gemm<<<dim3(NPK / BN, BSZ / BM), 256, SMEM_TOTAL>>>(c, out_h, out_c);
    head_kernel<<<(BSZ * 32 + 255) / 256, 256>>>(out_h, Wout, bout, pre_label);
}

// round 12
// speedup vs baseline: 2.4090x; 1.2383x over previous
#include <cuda_runtime.h>
#include <cuda_fp16.h>
#include <cstdint>
#include <math.h>

// Problem constants
#define BSZ   32768
#define HDIM  512
#define KTOT  1024          // concat(x,h)
#define NPK   2048          // 4 gates * 512, interleaved (j,gate): col = 4*j+g

// GEMM tiling (warp-level mma.sync path; base-PTX features only)
#define BM    128           // rows per CTA
#define BN    128           // packed cols per CTA (= 32 j's)
#define BK    64            // K per iteration
#define NCH   (KTOT / BK)   // 16 iterations
#define NST   3             // cp.async pipeline stages

// A: single fp16, row = 1024 fp16 = 2048B. B: 2-term fp16 split (hi, lo arrays).
__device__ __half g_Apk[(size_t)BSZ * KTOT];   // 64 MB
__device__ __half g_Bhi[(size_t)NPK * KTOT];   // 4 MB
__device__ __half g_Blo[(size_t)NPK * KTOT];   // 4 MB
__device__ float  g_bp[NPK];

// ---------------------------------------------------------------- helpers
__device__ __forceinline__ uint32_t smem_u32(const void* p) {
    uint32_t a;
    asm("{ .reg .u64 t; cvta.to.shared.u64 t, %1; cvt.u32.u64 %0, t; }" : "=r"(a) : "l"(p));
    return a;
}
__device__ __forceinline__ uint32_t swz(uint32_t off) {   // xor swizzle on 128B rows
    return off ^ ((off >> 3) & 0x70);
}
__device__ __forceinline__ void cpa16(uint32_t dst, const void* src) {
    asm volatile("cp.async.cg.shared.global [%0], [%1], 16;" :: "r"(dst), "l"(src) : "memory");
}
__device__ __forceinline__ void cpa_commit() { asm volatile("cp.async.commit_group;" ::: "memory"); }
__device__ __forceinline__ void cpa_wait1()  { asm volatile("cp.async.wait_group 1;" ::: "memory"); }
__device__ __forceinline__ void cpa_wait0()  { asm volatile("cp.async.wait_group 0;" ::: "memory"); }

__device__ __forceinline__ void ldsm4(uint32_t* r, uint32_t addr) {
    asm volatile("ldmatrix.sync.aligned.m8n8.x4.shared.b16 {%0,%1,%2,%3}, [%4];"
        : "=r"(r[0]), "=r"(r[1]), "=r"(r[2]), "=r"(r[3]) : "r"(addr));
}
__device__ __forceinline__ void mma16816(float* d, const uint32_t* a, const uint32_t* b) {
    asm volatile(
        "mma.sync.aligned.m16n8k16.row.col.f32.f16.f16.f32 "
        "{%0,%1,%2,%3}, {%4,%5,%6,%7}, {%8,%9}, {%0,%1,%2,%3};"
        : "+f"(d[0]), "+f"(d[1]), "+f"(d[2]), "+f"(d[3])
        : "r"(a[0]), "r"(a[1]), "r"(a[2]), "r"(a[3]), "r"(b[0]), "r"(b[1]));
}

// ---------------------------------------------------------------- pre-passes
// Each thread converts 8 consecutive k's of one row -> one 16B fp16 write.
__global__ void conv_A(const float* __restrict__ x, const float* __restrict__ h) {
    size_t t = (size_t)blockIdx.x * blockDim.x + threadIdx.x;
    if (t >= (size_t)BSZ * (KTOT / 8)) return;
    int row = (int)(t >> 7);            // 128 groups of 8 per row
    int kg  = ((int)t & 127) * 8;
    const float* src = (kg < HDIM) ? (x + (size_t)row * HDIM + kg)
                                   : (h + (size_t)row * HDIM + (kg - HDIM));
    float4 v0 = *(const float4*)(src);
    float4 v1 = *(const float4*)(src + 4);
    float v[8] = {v0.x, v0.y, v0.z, v0.w, v1.x, v1.y, v1.z, v1.w};
    __half o[8];
    #pragma unroll
    for (int e = 0; e < 8; e++) o[e] = __float2half(v[e]);
    *(uint4*)&g_Apk[(size_t)row * KTOT + kg] = *(uint4*)o;
}

__global__ void pack_W(
    const float* __restrict__ Uf, const float* __restrict__ Vf, const float* __restrict__ bf,
    const float* __restrict__ Ui, const float* __restrict__ Vi, const float* __restrict__ bi,
    const float* __restrict__ Uo, const float* __restrict__ Vo, const float* __restrict__ bo,
    const float* __restrict__ Uc, const float* __restrict__ Vc, const float* __restrict__ bc)
{
    int idx = blockIdx.x * blockDim.x + threadIdx.x;   // over KTOT*HDIM
    if (idx >= KTOT * HDIM) return;
    int j = idx & (HDIM - 1);
    int k = idx >> 9;
    const float* Us[4] = {Uf, Ui, Uo, Uc};
    const float* Vs[4] = {Vf, Vi, Vo, Vc};
    const float* bs[4] = {bf, bi, bo, bc};
    #pragma unroll
    for (int g = 0; g < 4; g++) {
        float v = (k < HDIM) ? Us[g][(size_t)k * HDIM + j]
                             : Vs[g][(size_t)(k - HDIM) * HDIM + j];
        __half hi = __float2half(v);
        __half lo = __float2half(v - __half2float(hi));
        size_t n = (size_t)(4 * j + g);
        g_Bhi[n * KTOT + k] = hi;
        g_Blo[n * KTOT + k] = lo;
        if (k == 0) g_bp[4 * j + g] = bs[g][j];
    }
}

// ---------------------------------------------------------------- main GEMM
// Stage (48KB): A 16KB | Bhi 16KB | Blo 16KB. Each: 128 rows x 128B (64 fp16),
// xor-swizzled within the 128B row.
#define STAGE_BYTES 49152
#define SMEM_TOTAL  (NST * STAGE_BYTES)

__device__ __forceinline__ void load_chunk(uint32_t st,
                                           const __half* Asrc,
                                           const __half* Bhsrc,
                                           const __half* Blsrc,
                                           int c, int tid)
{
    const char* ap = (const char*)Asrc;
    const char* bh = (const char*)Bhsrc;
    const char* bl = (const char*)Blsrc;
    #pragma unroll
    for (int kq = 0; kq < 4; kq++) {
        int q = tid + 256 * kq;            // 0..1023 16B-units per sub-tile
        int r = q >> 3, u = q & 7;
        uint32_t soff = swz((uint32_t)(r << 7) + (uint32_t)(u << 4));
        size_t go = ((size_t)r << 11) + ((size_t)c << 7) + ((size_t)u << 4);
        cpa16(st + soff, ap + go);
        cpa16(st + 16384 + soff, bh + go);
        cpa16(st + 32768 + soff, bl + go);
    }
}

__global__ void __launch_bounds__(256, 1) lstm_gemm(
    const float* __restrict__ c_in,
    float* __restrict__ out_h, float* __restrict__ out_c)
{
    extern __shared__ char smem[];
    uint32_t sb = smem_u32(smem);
    const int tid  = threadIdx.x;
    const int lane = tid & 31;
    const int wid  = tid >> 5;
    const int wm   = wid & 1;      // 2 warp-rows of 64
    const int wn   = wid >> 1;     // 4 warp-cols of 32
    const int brow = blockIdx.y * BM;
    const int bcol = blockIdx.x * BN;

    const __half* Asrc  = g_Apk + (size_t)brow * KTOT;
    const __half* Bhsrc = g_Bhi + (size_t)bcol * KTOT;
    const __half* Blsrc = g_Blo + (size_t)bcol * KTOT;

    float acc[4][4][4];
    #pragma unroll
    for (int mt = 0; mt < 4; mt++)
        #pragma unroll
        for (int nt = 0; nt < 4; nt++)
            #pragma unroll
            for (int e = 0; e < 4; e++) acc[mt][nt][e] = 0.f;

    // prologue: fill 2 stages
    load_chunk(sb + 0 * STAGE_BYTES, Asrc, Bhsrc, Blsrc, 0, tid); cpa_commit();
    load_chunk(sb + 1 * STAGE_BYTES, Asrc, Bhsrc, Blsrc, 1, tid); cpa_commit();

    // ldmatrix address components
    const int a_row = wm * 64 + (lane & 15);              // + mt*16
    const int a_kb  = (lane >> 4) * 16;                   // + g*32
    const int b_row = (lane & 7) + ((lane >> 4) & 1) * 8; // + wn*32 + ntp*16
    const int b_kb  = ((lane >> 3) & 1) * 16;             // + g*32

    for (int i = 0; i < NCH; i++) {
        if (i == NCH - 1) cpa_wait0(); else cpa_wait1();
        __syncthreads();

        if (i + 2 < NCH) {
            load_chunk(sb + ((i + 2) % 3) * STAGE_BYTES, Asrc, Bhsrc, Blsrc, i + 2, tid);
            cpa_commit();
        }

        uint32_t st = sb + (i % 3) * STAGE_BYTES;

        #pragma unroll
        for (int g = 0; g < 4; g++) {                     // 4 k16 groups in BK=64
            uint32_t kk = (uint32_t)(g * 32);
            uint32_t ah[4][4], bh[4][2], bl[4][2];
            #pragma unroll
            for (int mt = 0; mt < 4; mt++) {
                uint32_t roff = (uint32_t)((a_row + mt * 16) << 7);
                ldsm4(ah[mt], st + swz(roff + (uint32_t)a_kb + kk));
            }
            #pragma unroll
            for (int ntp = 0; ntp < 2; ntp++) {
                uint32_t roff = (uint32_t)((wn * 32 + ntp * 16 + b_row) << 7);
                uint32_t t4[4];
                ldsm4(t4, st + 16384 + swz(roff + (uint32_t)b_kb + kk));
                bh[2 * ntp][0] = t4[0]; bh[2 * ntp][1] = t4[1];
                bh[2 * ntp + 1][0] = t4[2]; bh[2 * ntp + 1][1] = t4[3];
                ldsm4(t4, st + 32768 + swz(roff + (uint32_t)b_kb + kk));
                bl[2 * ntp][0] = t4[0]; bl[2 * ntp][1] = t4[1];
                bl[2 * ntp + 1][0] = t4[2]; bl[2 * ntp + 1][1] = t4[3];
            }
            #pragma unroll
            for (int mt = 0; mt < 4; mt++)
                #pragma unroll
                for (int nt = 0; nt < 4; nt++) {
                    mma16816(acc[mt][nt], ah[mt], bh[nt]);   // a * b_hi
                    mma16816(acc[mt][nt], ah[mt], bl[nt]);   // a * b_lo
                }
        }
    }

    // -------- epilogue: gates in registers, h/c staged via SMEM (coalesced)
    __syncthreads();
    float* shC = (float*)smem;            // [128][33]
    float* shH = shC + 128 * 33;          // [128][33]
    const int j0 = bcol >> 2;             // 32 j's per CTA

    for (int idx = tid; idx < 128 * 32; idx += 256) {
        int r = idx >> 5, j = idx & 31;
        shC[r * 33 + j] = c_in[(size_t)(brow + r) * HDIM + j0 + j];
    }
    __syncthreads();

    #pragma unroll
    for (int mt = 0; mt < 4; mt++) {
        #pragma unroll
        for (int nt = 0; nt < 4; nt++) {
            int nb = wn * 32 + nt * 8 + 2 * (lane & 3);   // local packed col (pair base)
            float bA = __ldg(&g_bp[bcol + nb]);
            float bB = __ldg(&g_bp[bcol + nb + 1]);
            #pragma unroll
            for (int hf = 0; hf < 2; hf++) {
                int row = wm * 64 + mt * 16 + (lane >> 2) + hf * 8;
                float p0 = acc[mt][nt][2 * hf + 0] + bA;
                float p1 = acc[mt][nt][2 * hf + 1] + bB;
                float q0 = __shfl_xor_sync(0xffffffffu, p0, 1);
                float q1 = __shfl_xor_sync(0xffffffffu, p1, 1);
                if ((lane & 1) == 0) {
                    // even lane holds (f,i); partner lane holds (o,c)
                    float fg = 1.f / (1.f + __expf(-p0));
                    float ig = 1.f / (1.f + __expf(-p1));
                    float og = 1.f / (1.f + __expf(-q0));
                    float ch = tanhf(q1);
                    int jl = nb >> 2;
                    float co = shC[row * 33 + jl];
                    float cn = fg * co + ig * ch;
                    float hn = og * tanhf(cn);
                    shC[row * 33 + jl] = cn;
                    shH[row * 33 + jl] = hn;
                }
            }
        }
    }
    __syncthreads();

    for (int idx = tid; idx < 128 * 32; idx += 256) {
        int r = idx >> 5, j = idx & 31;
        size_t go = (size_t)(brow + r) * HDIM + j0 + j;
        out_h[go] = shH[r * 33 + j];
        out_c[go] = shC[r * 33 + j];
    }
}

// ---------------------------------------------------------------- head
__global__ void head_kernel(const float* __restrict__ hbuf,
                            const float* __restrict__ Wout,
                            const float* __restrict__ bout,
                            float* __restrict__ pre_label)
{
    int warp = (blockIdx.x * blockDim.x + threadIdx.x) >> 5;
    int lane = threadIdx.x & 31;
    if (warp >= BSZ) return;
    const float* row = hbuf + (size_t)warp * HDIM;
    float s0 = 0.f, s1 = 0.f;
    #pragma unroll 4
    for (int j = lane; j < HDIM; j += 32) {
        float v = row[j];
        s0 += v * Wout[j * 2 + 0];
        s1 += v * Wout[j * 2 + 1];
    }
    #pragma unroll
    for (int off = 16; off; off >>= 1) {
        s0 += __shfl_xor_sync(0xffffffffu, s0, off);
        s1 += __shfl_xor_sync(0xffffffffu, s1, off);
    }
    if (lane == 0) {
        s0 += bout[0];
        s1 += bout[1];
        float mx = fmaxf(s0, s1);
        float e0 = __expf(s0 - mx), e1 = __expf(s1 - mx);
        float inv = 1.f / (e0 + e1);
        pre_label[warp * 2 + 0] = e0 * inv;
        pre_label[warp * 2 + 1] = e1 * inv;
    }
}

// ---------------------------------------------------------------- launch
extern "C" void kernel_launch(void* const* d_in, const int* in_sizes, int n_in,
                              void* d_out, int out_size)
{
    const float* x    = (const float*)d_in[0];
    const float* h    = (const float*)d_in[1];
    const float* c    = (const float*)d_in[2];
    const float* Uf   = (const float*)d_in[3];
    const float* Vf   = (const float*)d_in[4];
    const float* bf   = (const float*)d_in[5];
    const float* Ui   = (const float*)d_in[6];
    const float* Vi   = (const float*)d_in[7];
    const float* bi   = (const float*)d_in[8];
    const float* Uo   = (const float*)d_in[9];
    const float* Vo   = (const float*)d_in[10];
    const float* bo   = (const float*)d_in[11];
    const float* Uc   = (const float*)d_in[12];
    const float* Vc   = (const float*)d_in[13];
    const float* bc   = (const float*)d_in[14];
    const float* Wout = (const float*)d_in[15];
    const float* bout = (const float*)d_in[16];

    float* out       = (float*)d_out;
    float* pre_label = out;                       // [B,2]
    float* out_h     = out + (size_t)BSZ * 2;     // [B,512]
    float* out_c     = out_h + (size_t)BSZ * HDIM;

    cudaFuncSetAttribute(lstm_gemm, cudaFuncAttributeMaxDynamicSharedMemorySize, SMEM_TOTAL);

    pack_W<<<(KTOT * HDIM + 255) / 256, 256>>>(Uf, Vf, bf, Ui, Vi, bi,
                                               Uo, Vo, bo, Uc, Vc, bc);
    conv_A<<<(int)(((size_t)BSZ * (KTOT / 8) + 255) / 256), 256>>>(x, h);
    lstm_gemm<<<dim3(NPK / BN, BSZ / BM), 256, SMEM_TOTAL>>>(c, out_h, out_c);
    head_kernel<<<(BSZ * 32 + 255) / 256, 256>>>(out_h, Wout, bout, pre_label);
}